// round 13
// baseline (speedup 1.0000x reference)
#include <cuda_runtime.h>
#include <cuda_fp16.h>
#include <cstdint>
#include <cstddef>

#define Bv   4
#define Sv   4096
#define Dv   256
#define Hv   4
#define DEP  64
#define DFFv 1024
#define MTOK (Bv*Sv)
#define NQKV (3*Dv)
#define S_LOG2E 0.18033688011112042f   /* 0.125 * log2(e) */

// ---------------- scratch (device globals) ------------------------------------
__device__ float  g_X1[MTOK*Dv];
__device__ float  g_H [(size_t)MTOK*DFFv];
__device__ float  g_negm[Bv*Sv];
__device__ float  g_bqkv[NQKV];
__device__ __half g_xh   [MTOK*Dv];
__device__ __half g_QKVh [(size_t)MTOK*NQKV];
__device__ __half g_ctxh [MTOK*Dv];
__device__ __half g_x1h  [MTOK*Dv];
__device__ __half g_hh   [(size_t)MTOK*DFFv];
__device__ __half g_wqkvT[(size_t)NQKV*Dv];
__device__ __half g_woT[Dv*Dv];
__device__ __half g_w1T[(size_t)DFFv*Dv];
__device__ __half g_w2T[(size_t)Dv*DFFv];

// ---------------- helpers ------------------------------------------------------
__device__ __forceinline__ uint32_t sm32(const void* p){
    return (uint32_t)__cvta_generic_to_shared(p);
}
__device__ __forceinline__ void cpa16(void* s, const void* g){
    asm volatile("cp.async.cg.shared.global [%0], [%1], 16;"
                 :: "r"(sm32(s)), "l"(g));
}
__device__ __forceinline__ void cpa_commit(){
    asm volatile("cp.async.commit_group;");
}
template<int N> __device__ __forceinline__ void cpa_wait(){
    asm volatile("cp.async.wait_group %0;" :: "n"(N));
}
__device__ __forceinline__ void mma_f16(float* c, const uint32_t* a,
                                        uint32_t b0, uint32_t b1){
    asm volatile(
      "mma.sync.aligned.m16n8k16.row.col.f32.f16.f16.f32 "
      "{%0,%1,%2,%3},{%4,%5,%6,%7},{%8,%9},{%0,%1,%2,%3};\n"
      : "+f"(c[0]), "+f"(c[1]), "+f"(c[2]), "+f"(c[3])
      : "r"(a[0]), "r"(a[1]), "r"(a[2]), "r"(a[3]), "r"(b0), "r"(b1));
}
__device__ __forceinline__ uint32_t pack2(float a, float b){
    __half2 h = __floats2half2_rn(a, b);
    return *reinterpret_cast<uint32_t*>(&h);
}
__device__ __forceinline__ uint32_t lds32(const __half* p){
    return *reinterpret_cast<const uint32_t*>(p);
}
__device__ __forceinline__ uint2 lds64(const __half* p){
    return *reinterpret_cast<const uint2*>(p);
}
__device__ __forceinline__ float ex2(float x){
    float y; asm("ex2.approx.ftz.f32 %0, %1;" : "=f"(y) : "f"(x)); return y;
}
// pack {lo=lo_src, hi=hi_src} into f16x2
__device__ __forceinline__ uint32_t cvtf16x2(float hi_src, float lo_src){
    uint32_t d;
    asm("cvt.rn.f16x2.f32 %0, %1, %2;" : "=r"(d) : "f"(hi_src), "f"(lo_src));
    return d;
}
__device__ __forceinline__ uint32_t h2ex2(uint32_t x){
    uint32_t d;
    asm("ex2.approx.f16x2 %0, %1;" : "=r"(d) : "r"(x));
    return d;
}
__device__ __forceinline__ float2 h2tof2(uint32_t x){
    __half2 h = *reinterpret_cast<__half2*>(&x);
    return __half22float2(h);
}

// ---------------- prep: fp32 -> fp16 -------------------------------------------
__global__ __launch_bounds__(256) void cvt_kernel(
    const float* __restrict__ in, __half* __restrict__ out, int n4)
{
    int i = blockIdx.x * blockDim.x + threadIdx.x;
    if (i < n4){
        float4 v = reinterpret_cast<const float4*>(in)[i];
        uint2 u;
        u.x = pack2(v.x, v.y);
        u.y = pack2(v.z, v.w);
        reinterpret_cast<uint2*>(out)[i] = u;
    }
}

// ---------------- prep: concat qkv bias ----------------------------------------
__global__ __launch_bounds__(256) void prep_bias(
    const float* __restrict__ bq, const float* __restrict__ bk,
    const float* __restrict__ bv, float* __restrict__ bqkv)
{
    int i = blockIdx.x * blockDim.x + threadIdx.x;
    if (i < NQKV)
        bqkv[i] = (i < Dv) ? bq[i] : (i < 2*Dv) ? bk[i - Dv] : bv[i - 2*Dv];
}

// ---------------- prep: log2e-premultiplied mask -------------------------------
__global__ __launch_bounds__(256) void prep_mask(
    const float* __restrict__ mask, float* __restrict__ negm)
{
    int j = blockIdx.x * blockDim.x + threadIdx.x;
    if (j < Bv*Sv)
        negm[j] = -1.4426950408889634e9f * mask[j];
}

// ---------------- prep: all weight transposes ----------------------------------
__device__ __forceinline__ void transp_tile(
    const float* __restrict__ in, __half* __restrict__ out,
    int R, int C, int bx, int by)
{
    __shared__ float t[32][33];
    int tx = threadIdx.x, ty = threadIdx.y;         // block (32,8)
    #pragma unroll
    for (int j = 0; j < 32; j += 8)
        t[ty + j][tx] = in[(size_t)(by + ty + j) * C + bx + tx];
    __syncthreads();
    #pragma unroll
    for (int j = 0; j < 32; j += 8)
        out[(size_t)(bx + ty + j) * R + by + tx] = __float2half_rn(t[tx][ty + j]);
}

__global__ __launch_bounds__(256) void transp_all(
    const float* wq, const float* wk, const float* wv, const float* wo,
    const float* w1, const float* w2,
    __half* wqkvT, __half* woT, __half* w1T, __half* w2T)
{
    int bid = blockIdx.x;   // 0..767
    if (bid < 256){
        int m = bid >> 6, t = bid & 63;
        int bx = (t & 7) * 32, by = (t >> 3) * 32;
        const float* in  = (m==0)? wq : (m==1)? wk : (m==2)? wv : wo;
        __half*      outp= (m==3)? woT : wqkvT + (size_t)m * Dv * Dv;
        transp_tile(in, outp, Dv, Dv, bx, by);
    } else if (bid < 512){
        int t = bid - 256;
        int bx = (t & 31) * 32, by = (t >> 5) * 32;
        transp_tile(w1, w1T, Dv, DFFv, bx, by);
    } else {
        int t = bid - 512;
        int bx = (t & 7) * 32, by = (t >> 3) * 32;
        transp_tile(w2, w2T, DFFv, Dv, bx, by);
    }
}

// ---------------- fp16 GEMM: 3-stage ring, LDS.64 k-interleaved (proven R7) -----
#define GST 80
#define GEMM_SMEM_BYTES ((3*128*GST + 3*64*GST)*2)

template<bool RELU, bool HOUT>
__global__ __launch_bounds__(256) void gemm_h(
    const __half* __restrict__ A, const __half* __restrict__ Bt,
    const float* __restrict__ bias, const float* __restrict__ res,
    float* __restrict__ Yf, __half* __restrict__ Yh, int M, int N, int K)
{
    extern __shared__ char gsm[];
    __half* As = reinterpret_cast<__half*>(gsm);          // 3 stages [128][GST]
    __half* Bs = As + 3*128*GST;                          // 3 stages [64][GST]

    const int tid  = threadIdx.x;
    const int lane = tid & 31;
    const int gid  = lane >> 2, tig = lane & 3;
    const int wid  = tid >> 5;
    const int wm   = wid >> 1, wn = wid & 1;
    const int bm   = blockIdx.y * 128, bn = blockIdx.x * 64;

    float acc[2][4][4];
    #pragma unroll
    for (int i = 0; i < 2; i++)
        #pragma unroll
        for (int j = 0; j < 4; j++)
            #pragma unroll
            for (int k = 0; k < 4; k++) acc[i][j][k] = 0.f;

    const int ar  = tid >> 2;           // A row 0..63 (+64)
    const int ac  = (tid & 3) * 8;      // A col chunk (16B)
    const int bn_ = tid >> 2;           // B n row 0..63
    const int bc  = (tid & 3) * 8;      // B k chunk

    auto stage = [&](int k0, int st){
        __half* Ad = As + st*128*GST;
        __half* Bd = Bs + st*64*GST;
        #pragma unroll
        for (int ir = 0; ir < 2; ir++){
            int r = ar + ir * 64;
            cpa16(&Ad[r * GST + ac], A + (size_t)(bm + r) * K + k0 + ac);
        }
        cpa16(&Bd[bn_ * GST + bc], Bt + (size_t)(bn + bn_) * K + k0 + bc);
        cpa_commit();
    };

    const int KIT = K >> 5;
    stage(0, 0);
    stage(32, 1);

    for (int it = 0; it < KIT; it++){
        if (it + 1 < KIT) cpa_wait<1>(); else cpa_wait<0>();
        __syncthreads();
        if (it + 2 < KIT) stage((it + 2) * 32, (it + 2) % 3);

        const __half* Ab = As + (it % 3)*128*GST;
        const __half* Bb = Bs + (it % 3)*64*GST;
        #pragma unroll
        for (int ks = 0; ks < 2; ks++){
            const int kc = ks * 16 + 4 * tig;      // interleaved k chunk
            uint32_t af[2][4];
            #pragma unroll
            for (int mt = 0; mt < 2; mt++){
                int r0 = wm*32 + mt*16 + gid;
                uint2 lo = lds64(&Ab[ r0      * GST + kc]);
                uint2 hi = lds64(&Ab[(r0 + 8) * GST + kc]);
                af[mt][0] = lo.x; af[mt][2] = lo.y;
                af[mt][1] = hi.x; af[mt][3] = hi.y;
            }
            #pragma unroll
            for (int nt = 0; nt < 4; nt++){
                uint2 bv = lds64(&Bb[(wn*32 + nt*8 + gid) * GST + kc]);
                #pragma unroll
                for (int mt = 0; mt < 2; mt++)
                    mma_f16(acc[mt][nt], af[mt], bv.x, bv.y);
            }
        }
    }

    #pragma unroll
    for (int mt = 0; mt < 2; mt++){
        #pragma unroll
        for (int nt = 0; nt < 4; nt++){
            int col = bn + wn * 32 + nt * 8 + 2 * tig;
            float b0 = bias[col], b1 = bias[col + 1];
            int r0 = bm + wm * 32 + mt * 16 + gid;
            #pragma unroll
            for (int hf = 0; hf < 2; hf++){
                int row = r0 + hf * 8;
                float v0 = acc[mt][nt][hf*2+0] + b0;
                float v1 = acc[mt][nt][hf*2+1] + b1;
                if (res){
                    v0 += res[(size_t)row * N + col];
                    v1 += res[(size_t)row * N + col + 1];
                }
                if (RELU){ v0 = fmaxf(v0, 0.f); v1 = fmaxf(v1, 0.f); }
                if (HOUT){
                    __half2 hv = __floats2half2_rn(v0, v1);
                    *reinterpret_cast<__half2*>(Yh + (size_t)row * N + col) = hv;
                } else {
                    *reinterpret_cast<float2*>(Yf + (size_t)row * N + col) = make_float2(v0, v1);
                }
            }
        }
    }
}

// ---------------- flash attention ----------------------------------------------
// CTA: 256 queries of one (b,h); 8 warps x 32 q-rows; 32 key-tiles of 128.
// sVT key-permuted within 16-key groups so PV (b0,b1) is one LDS.64.
// Softmax: log2 domain; masks dedup'd (2 distinct values per nt, broadcast
// float2 LDS shared across mt); tree rmax/rsum; f16x2 exp interleaved with PV.
#define QST  80
#define KST2 80
#define VST  72
#define VTST 136
#define NT_TILES (Sv/128)
#define QROWS 256
#define ATTN_SMEM_BYTES ((QROWS*QST + 2*128*KST2 + 2*128*VST + 64*VTST)*2 + 2*128*4)

__global__ __launch_bounds__(256, 1) void attn_h(
    const __half* __restrict__ QKV, const float* __restrict__ negm,
    __half* __restrict__ O)
{
    extern __shared__ char smem_raw[];
    __half* sQ  = reinterpret_cast<__half*>(smem_raw);
    __half* sK0 = sQ  + QROWS*QST;
    __half* sK1 = sK0 + 128*KST2;
    __half* sV0 = sK1 + 128*KST2;
    __half* sV1 = sV0 + 128*VST;
    __half* sVT = sV1 + 128*VST;
    float* sMask0 = reinterpret_cast<float*>(sVT + 64*VTST);
    float* sMask1 = sMask0 + 128;

    const int tid = threadIdx.x, lane = tid & 31, wid = tid >> 5;
    const int gid = lane >> 2, tig = lane & 3;
    const int m0  = wid * 32;
    const int b   = blockIdx.y >> 2, h = blockIdx.y & 3;
    const int q0  = blockIdx.x * QROWS;
    const __half* Qb = QKV + (size_t)b*Sv*NQKV + (size_t)h*DEP;
    const __half* Kb = Qb + Dv;
    const __half* Vb = Qb + 2*Dv;
    const float*  Mb = negm + (size_t)b*Sv;

    const int sr  = tid >> 2;            // staging row 0..63
    const int sc  = (tid & 3) * 16;      // staging col (two 16B chunks)

    auto stageKVM = [&](int kt, __half* dK, __half* dV, float* dM){
        const int kbase = kt * 128;
        #pragma unroll
        for (int ir = 0; ir < 2; ir++){
            int row = sr + ir * 64;
            const __half* ks_ = Kb + (size_t)(kbase + row) * NQKV + sc;
            cpa16(&dK[row*KST2 + sc    ], ks_);
            cpa16(&dK[row*KST2 + sc + 8], ks_ + 8);
            const __half* vs_ = Vb + (size_t)(kbase + row) * NQKV + sc;
            cpa16(&dV[row*VST + sc    ], vs_);
            cpa16(&dV[row*VST + sc + 8], vs_ + 8);
        }
        if (tid < 32) cpa16(&dM[tid*4], Mb + kbase + tid*4);
    };

    // prologue: Q (256 rows) + tile0
    {
        #pragma unroll
        for (int ir = 0; ir < 4; ir++){
            int row = sr + ir * 64;
            const __half* src = Qb + (size_t)(q0 + row) * NQKV + sc;
            cpa16(&sQ[row*QST + sc    ], src);
            cpa16(&sQ[row*QST + sc + 8], src + 8);
        }
        stageKVM(0, sK0, sV0, sMask0);
        cpa_commit();
    }
    cpa_wait<0>();
    __syncthreads();

    // Q fragments in registers, k-interleaved layout (LDS.64)
    uint32_t qf[2][4][4];
    #pragma unroll
    for (int mt = 0; mt < 2; mt++){
        #pragma unroll
        for (int kd = 0; kd < 4; kd++){
            int r0 = m0 + mt*16 + gid;
            uint2 lo = lds64(&sQ[ r0      * QST + kd*16 + 4*tig]);
            uint2 hi = lds64(&sQ[(r0 + 8) * QST + kd*16 + 4*tig]);
            qf[mt][kd][0] = lo.x; qf[mt][kd][2] = lo.y;
            qf[mt][kd][1] = hi.x; qf[mt][kd][3] = hi.y;
        }
    }

    float o[2][8][4];
    #pragma unroll
    for (int mt = 0; mt < 2; mt++)
        #pragma unroll
        for (int i = 0; i < 8; i++){
            o[mt][i][0]=o[mt][i][1]=o[mt][i][2]=o[mt][i][3]=0.f;
        }
    float mrow[2][2] = {{-1e30f,-1e30f},{-1e30f,-1e30f}};
    float lrow[2][2] = {{0.f,0.f},{0.f,0.f}};

    const int vkp = tid & 63;            // V-transpose key pair index
    const int vdb = (tid >> 6) * 8;      // V-transpose d base
    const int vgrp = vkp >> 3, vt = vkp & 7;
    const int vslot = (vt < 4) ? (2*vt) : (2*(vt-4) + 1);
    const int vhoff = vgrp*16 + vslot*2;  // half offset of this pair in sVT row

    for (int kt = 0; kt < NT_TILES; kt++){
        const int buf = kt & 1;
        __half* cK = buf ? sK1 : sK0;
        __half* cV = buf ? sV1 : sV0;
        float*  cM = buf ? sMask1 : sMask0;
        const bool nxt = (kt + 1 < NT_TILES);
        if (nxt){
            stageKVM(kt + 1, buf ? sK0 : sK1, buf ? sV0 : sV1,
                     buf ? sMask0 : sMask1);
            cpa_commit();
        }

        // transpose V: cV[key][d] -> sVT[d][perm(key)]
        #pragma unroll
        for (int it = 0; it < 2; it++){
            int d0 = vdb + it * 32;
            uint4 va = *reinterpret_cast<const uint4*>(&cV[(2*vkp    )*VST + d0]);
            uint4 vb = *reinterpret_cast<const uint4*>(&cV[(2*vkp + 1)*VST + d0]);
            const __half* ha = reinterpret_cast<const __half*>(&va);
            const __half* hb = reinterpret_cast<const __half*>(&vb);
            #pragma unroll
            for (int j = 0; j < 8; j++){
                __half2 pr = __halves2half2(ha[j], hb[j]);
                *reinterpret_cast<uint32_t*>(&sVT[(d0+j)*VTST + vhoff]) =
                    *reinterpret_cast<uint32_t*>(&pr);
            }
        }

        #pragma unroll
        for (int hh2 = 0; hh2 < 2; hh2++){
            const int kh0 = hh2 * 64;
            // ---- S = Q @ K^T over 64 keys, shared B-fragments ----
            float p[2][8][4];
            #pragma unroll
            for (int mt = 0; mt < 2; mt++)
                #pragma unroll
                for (int nt = 0; nt < 8; nt++){
                    p[mt][nt][0]=p[mt][nt][1]=p[mt][nt][2]=p[mt][nt][3]=0.f;
                }
            #pragma unroll
            for (int kd = 0; kd < 4; kd++){
                #pragma unroll
                for (int nt = 0; nt < 8; nt++){
                    uint2 bv = lds64(&cK[(kh0 + nt*8 + gid)*KST2 + kd*16 + 4*tig]);
                    mma_f16(p[0][nt], qf[0][kd], bv.x, bv.y);
                    mma_f16(p[1][nt], qf[1][kd], bv.x, bv.y);
                }
            }
            if (hh2 == 0) __syncthreads();   // sVT + masks visible before use

            // ---- masks: 2 distinct values per nt, shared by both mt ----
            float2 mnt[8];
            #pragma unroll
            for (int nt = 0; nt < 8; nt++)
                mnt[nt] = *reinterpret_cast<const float2*>(&cM[kh0 + nt*8 + 2*tig]);

            // ---- scale+mask, tree rmax, alpha, o-rescale (per mt) ----
            float mnew[2][2], alpha2[2][2];
            #pragma unroll
            for (int mt = 0; mt < 2; mt++){
                #pragma unroll
                for (int nt = 0; nt < 8; nt++){
                    p[mt][nt][0] = fmaf(p[mt][nt][0], S_LOG2E, mnt[nt].x);
                    p[mt][nt][1] = fmaf(p[mt][nt][1], S_LOG2E, mnt[nt].y);
                    p[mt][nt][2] = fmaf(p[mt][nt][2], S_LOG2E, mnt[nt].x);
                    p[mt][nt][3] = fmaf(p[mt][nt][3], S_LOG2E, mnt[nt].y);
                }
                // tree max per row-half
                float a0[8], a1[8];
                #pragma unroll
                for (int nt = 0; nt < 8; nt++){
                    a0[nt] = fmaxf(p[mt][nt][0], p[mt][nt][1]);
                    a1[nt] = fmaxf(p[mt][nt][2], p[mt][nt][3]);
                }
                #pragma unroll
                for (int st = 4; st; st >>= 1)
                    #pragma unroll
                    for (int i = 0; i < st; i++){
                        a0[i] = fmaxf(a0[i], a0[i+st]);
                        a1[i] = fmaxf(a1[i], a1[i+st]);
                    }
                float rmax0 = a0[0], rmax1 = a1[0];
                rmax0 = fmaxf(rmax0, __shfl_xor_sync(0xffffffffu, rmax0, 1));
                rmax0 = fmaxf(rmax0, __shfl_xor_sync(0xffffffffu, rmax0, 2));
                rmax1 = fmaxf(rmax1, __shfl_xor_sync(0xffffffffu, rmax1, 1));
                rmax1 = fmaxf(rmax1, __shfl_xor_sync(0xffffffffu, rmax1, 2));
                mnew[mt][0] = fmaxf(mrow[mt][0], rmax0);
                mnew[mt][1] = fmaxf(mrow[mt][1], rmax1);
                alpha2[mt][0] = ex2(mrow[mt][0] - mnew[mt][0]);
                alpha2[mt][1] = ex2(mrow[mt][1] - mnew[mt][1]);
                mrow[mt][0] = mnew[mt][0];
                mrow[mt][1] = mnew[mt][1];
                #pragma unroll
                for (int nt = 0; nt < 8; nt++){
                    o[mt][nt][0] *= alpha2[mt][0]; o[mt][nt][1] *= alpha2[mt][0];
                    o[mt][nt][2] *= alpha2[mt][1]; o[mt][nt][3] *= alpha2[mt][1];
                }
            }

            // ---- exp (f16x2) interleaved with PV per ks chunk ----
            float rs0[2][2] = {{0.f,0.f},{0.f,0.f}};   // [mt][hh] partial A
            float rs1[2][2] = {{0.f,0.f},{0.f,0.f}};   // [mt][hh] partial B
            #pragma unroll
            for (int ks = 0; ks < 4; ks++){
                uint32_t ap[2][4];
                #pragma unroll
                for (int mt = 0; mt < 2; mt++){
                    #pragma unroll
                    for (int q = 0; q < 2; q++){
                        int nt = 2*ks + q;
                        float t0 = p[mt][nt][0] - mnew[mt][0];
                        float t1 = p[mt][nt][1] - mnew[mt][0];
                        float t2 = p[mt][nt][2] - mnew[mt][1];
                        float t3 = p[mt][nt][3] - mnew[mt][1];
                        uint32_t e01 = h2ex2(cvtf16x2(t1, t0));
                        uint32_t e23 = h2ex2(cvtf16x2(t3, t2));
                        ap[mt][2*q    ] = e01;
                        ap[mt][2*q + 1] = e23;
                        float2 f01 = h2tof2(e01);
                        float2 f23 = h2tof2(e23);
                        if (q == 0){ rs0[mt][0] += f01.x + f01.y;
                                     rs0[mt][1] += f23.x + f23.y; }
                        else       { rs1[mt][0] += f01.x + f01.y;
                                     rs1[mt][1] += f23.x + f23.y; }
                    }
                }
                #pragma unroll
                for (int nt2 = 0; nt2 < 8; nt2++){
                    uint2 bv = lds64(&sVT[(nt2*8 + gid)*VTST + kh0 + ks*16 + 4*tig]);
                    mma_f16(o[0][nt2], ap[0], bv.x, bv.y);
                    mma_f16(o[1][nt2], ap[1], bv.x, bv.y);
                }
            }

            // ---- finalize l ----
            #pragma unroll
            for (int mt = 0; mt < 2; mt++){
                #pragma unroll
                for (int hh = 0; hh < 2; hh++){
                    float rsum = rs0[mt][hh] + rs1[mt][hh];
                    rsum += __shfl_xor_sync(0xffffffffu, rsum, 1);
                    rsum += __shfl_xor_sync(0xffffffffu, rsum, 2);
                    lrow[mt][hh] = lrow[mt][hh] * alpha2[mt][hh] + rsum;
                }
            }
        }
        if (nxt) cpa_wait<0>();
        __syncthreads();
    }

    #pragma unroll
    for (int mt = 0; mt < 2; mt++){
        float inv0 = 1.f / lrow[mt][0], inv1 = 1.f / lrow[mt][1];
        #pragma unroll
        for (int nt = 0; nt < 8; nt++){
            int col  = h * DEP + nt * 8 + 2 * tig;
            int row0 = q0 + m0 + mt*16 + gid;
            __half2 h0 = __floats2half2_rn(o[mt][nt][0]*inv0, o[mt][nt][1]*inv0);
            __half2 h1 = __floats2half2_rn(o[mt][nt][2]*inv1, o[mt][nt][3]*inv1);
            *reinterpret_cast<__half2*>(O + (size_t)(b*Sv + row0    )*Dv + col) = h0;
            *reinterpret_cast<__half2*>(O + (size_t)(b*Sv + row0 + 8)*Dv + col) = h1;
        }
    }
}

// ---------------- LayerNorm: warp per row --------------------------------------
__global__ __launch_bounds__(256) void ln_kernel(
    const float* __restrict__ in, float* __restrict__ out, __half* __restrict__ outh,
    const float* __restrict__ g, const float* __restrict__ bt,
    int N, float eps)
{
    const int lane = threadIdx.x & 31;
    const int row  = blockIdx.x * 8 + (threadIdx.x >> 5);
    const int nch  = N >> 7;
    const float* x = in + (size_t)row * N;

    float4 v[8];
    float s = 0.f;
    for (int j = 0; j < nch; j++){
        v[j] = *reinterpret_cast<const float4*>(x + j*128 + lane*4);
        s += v[j].x + v[j].y + v[j].z + v[j].w;
    }
    #pragma unroll
    for (int o = 16; o; o >>= 1) s += __shfl_xor_sync(0xffffffffu, s, o);
    float mu = s / N;
    float var = 0.f;
    for (int j = 0; j < nch; j++){
        float dx = v[j].x-mu, dy = v[j].y-mu, dz = v[j].z-mu, dw = v[j].w-mu;
        var += dx*dx + dy*dy + dz*dz + dw*dw;
    }
    #pragma unroll
    for (int o = 16; o; o >>= 1) var += __shfl_xor_sync(0xffffffffu, var, o);
    float rstd = rsqrtf(var / N + eps);

    for (int j = 0; j < nch; j++){
        int c = j*128 + lane*4;
        float4 gg = *reinterpret_cast<const float4*>(g  + c);
        float4 bb = *reinterpret_cast<const float4*>(bt + c);
        float y0 = (v[j].x - mu) * rstd * gg.x + bb.x;
        float y1 = (v[j].y - mu) * rstd * gg.y + bb.y;
        float y2 = (v[j].z - mu) * rstd * gg.z + bb.z;
        float y3 = (v[j].w - mu) * rstd * gg.w + bb.w;
        if (out)
            *reinterpret_cast<float4*>(out + (size_t)row * N + c) =
                make_float4(y0, y1, y2, y3);
        if (outh){
            uint2 u;
            u.x = pack2(y0, y1);
            u.y = pack2(y2, y3);
            *reinterpret_cast<uint2*>(outh + (size_t)row * N + c) = u;
        }
    }
}

// ---------------- launch --------------------------------------------------------
extern "C" void kernel_launch(void* const* d_in, const int* in_sizes, int n_in,
                              void* d_out, int out_size)
{
    (void)in_sizes; (void)n_in; (void)out_size;
    const float* x    = (const float*)d_in[0];
    const float* mask = (const float*)d_in[1];
    const float* wq   = (const float*)d_in[2];
    const float* bq   = (const float*)d_in[3];
    const float* wk   = (const float*)d_in[4];
    const float* bk   = (const float*)d_in[5];
    const float* wv   = (const float*)d_in[6];
    const float* bv   = (const float*)d_in[7];
    const float* wo   = (const float*)d_in[8];
    const float* bo   = (const float*)d_in[9];
    const float* w1   = (const float*)d_in[10];
    const float* b1   = (const float*)d_in[11];
    const float* lnffg= (const float*)d_in[12];
    const float* lnffb= (const float*)d_in[13];
    const float* w2   = (const float*)d_in[14];
    const float* b2   = (const float*)d_in[15];
    const float* ln1g = (const float*)d_in[16];
    const float* ln1b = (const float*)d_in[17];
    const float* ln2g = (const float*)d_in[18];
    const float* ln2b = (const float*)d_in[19];
    float* out = (float*)d_out;

    float  *X1, *Hb, *negm, *bqkv;
    __half *xh, *QKVh, *ctxh, *x1h, *hh;
    __half *wqkvT, *woT, *w1T, *w2T;
    cudaGetSymbolAddress((void**)&X1,    g_X1);
    cudaGetSymbolAddress((void**)&Hb,    g_H);
    cudaGetSymbolAddress((void**)&negm,  g_negm);
    cudaGetSymbolAddress((void**)&bqkv,  g_bqkv);
    cudaGetSymbolAddress((void**)&xh,    g_xh);
    cudaGetSymbolAddress((void**)&QKVh,  g_QKVh);
    cudaGetSymbolAddress((void**)&ctxh,  g_ctxh);
    cudaGetSymbolAddress((void**)&x1h,   g_x1h);
    cudaGetSymbolAddress((void**)&hh,    g_hh);
    cudaGetSymbolAddress((void**)&wqkvT, g_wqkvT);
    cudaGetSymbolAddress((void**)&woT,   g_woT);
    cudaGetSymbolAddress((void**)&w1T,   g_w1T);
    cudaGetSymbolAddress((void**)&w2T,   g_w2T);

    cudaFuncSetAttribute(attn_h, cudaFuncAttributeMaxDynamicSharedMemorySize,
                         ATTN_SMEM_BYTES);
    cudaFuncSetAttribute(gemm_h<false,true>,  cudaFuncAttributeMaxDynamicSharedMemorySize, GEMM_SMEM_BYTES);
    cudaFuncSetAttribute(gemm_h<false,false>, cudaFuncAttributeMaxDynamicSharedMemorySize, GEMM_SMEM_BYTES);
    cudaFuncSetAttribute(gemm_h<true,false>,  cudaFuncAttributeMaxDynamicSharedMemorySize, GEMM_SMEM_BYTES);

    const dim3 blk(256);
    const dim3 gQKV(NQKV/64, MTOK/128);
    const dim3 gP(Dv/64,    MTOK/128);
    const dim3 gF(DFFv/64,  MTOK/128);

    // prep (negm deferred so attention is launch #6 for ncu -s 5 -c 1)
    cvt_kernel<<<(MTOK*Dv/4 + 255)/256, blk>>>(x, xh, MTOK*Dv/4);          // 1
    prep_bias<<<(NQKV + 255)/256, blk>>>(bq, bk, bv, bqkv);                // 2
    transp_all<<<768, dim3(32,8)>>>(wq, wk, wv, wo, w1, w2,
                                    wqkvT, woT, w1T, w2T);                 // 3
    gemm_h<false,true><<<gQKV, blk, GEMM_SMEM_BYTES>>>(xh, wqkvT, bqkv, nullptr,
                                                       nullptr, QKVh, MTOK, NQKV, Dv); // 4
    prep_mask<<<(Bv*Sv + 255)/256, blk>>>(mask, negm);                     // 5
    attn_h<<<dim3(Sv/QROWS, Bv*Hv), blk, ATTN_SMEM_BYTES>>>(QKVh, negm, ctxh); // 6
    // out-proj + residual, LN1
    gemm_h<false,false><<<gP, blk, GEMM_SMEM_BYTES>>>(ctxh, woT, bo, x, X1, nullptr,
                                                      MTOK, Dv, Dv);
    ln_kernel<<<MTOK/8, blk>>>(X1, X1, x1h, ln1g, ln1b, Dv, 1e-3f);
    // FFN1 + relu, LN_ff
    gemm_h<true,false><<<gF, blk, GEMM_SMEM_BYTES>>>(x1h, w1T, b1, nullptr, Hb, nullptr,
                                                     MTOK, DFFv, Dv);
    ln_kernel<<<MTOK/8, blk>>>(Hb, nullptr, hh, lnffg, lnffb, DFFv, 1e-6f);
    // FFN2 + residual, LN2
    gemm_h<false,false><<<gP, blk, GEMM_SMEM_BYTES>>>(hh, w2T, b2, X1, out, nullptr,
                                                      MTOK, Dv, DFFv);
    ln_kernel<<<MTOK/8, blk>>>(out, out, nullptr, ln2g, ln2b, Dv, 1e-3f);
}

// round 14
// speedup vs baseline: 1.0314x; 1.0314x over previous
#include <cuda_runtime.h>
#include <cuda_fp16.h>
#include <cstdint>
#include <cstddef>

#define Bv   4
#define Sv   4096
#define Dv   256
#define Hv   4
#define DEP  64
#define DFFv 1024
#define MTOK (Bv*Sv)
#define NQKV (3*Dv)
#define S_LOG2E 0.18033688011112042f   /* 0.125 * log2(e) */

// ---------------- scratch (device globals) ------------------------------------
__device__ float  g_X1[MTOK*Dv];
__device__ float  g_H [(size_t)MTOK*DFFv];
__device__ float  g_negm[Bv*Sv];
__device__ float  g_bqkv[NQKV];
__device__ __half g_xh   [MTOK*Dv];
__device__ __half g_QKVh [(size_t)MTOK*NQKV];
__device__ __half g_ctxh [MTOK*Dv];
__device__ __half g_x1h  [MTOK*Dv];
__device__ __half g_hh   [(size_t)MTOK*DFFv];
__device__ __half g_wqkvT[(size_t)NQKV*Dv];
__device__ __half g_woT[Dv*Dv];
__device__ __half g_w1T[(size_t)DFFv*Dv];
__device__ __half g_w2T[(size_t)Dv*DFFv];

// ---------------- helpers ------------------------------------------------------
__device__ __forceinline__ uint32_t sm32(const void* p){
    return (uint32_t)__cvta_generic_to_shared(p);
}
__device__ __forceinline__ void cpa16(void* s, const void* g){
    asm volatile("cp.async.cg.shared.global [%0], [%1], 16;"
                 :: "r"(sm32(s)), "l"(g));
}
__device__ __forceinline__ void cpa_commit(){
    asm volatile("cp.async.commit_group;");
}
template<int N> __device__ __forceinline__ void cpa_wait(){
    asm volatile("cp.async.wait_group %0;" :: "n"(N));
}
__device__ __forceinline__ void mma_f16(float* c, const uint32_t* a,
                                        uint32_t b0, uint32_t b1){
    asm volatile(
      "mma.sync.aligned.m16n8k16.row.col.f32.f16.f16.f32 "
      "{%0,%1,%2,%3},{%4,%5,%6,%7},{%8,%9},{%0,%1,%2,%3};\n"
      : "+f"(c[0]), "+f"(c[1]), "+f"(c[2]), "+f"(c[3])
      : "r"(a[0]), "r"(a[1]), "r"(a[2]), "r"(a[3]), "r"(b0), "r"(b1));
}
__device__ __forceinline__ uint32_t pack2(float a, float b){
    __half2 h = __floats2half2_rn(a, b);
    return *reinterpret_cast<uint32_t*>(&h);
}
__device__ __forceinline__ uint32_t lds32(const __half* p){
    return *reinterpret_cast<const uint32_t*>(p);
}
__device__ __forceinline__ uint2 lds64(const __half* p){
    return *reinterpret_cast<const uint2*>(p);
}
__device__ __forceinline__ float ex2(float x){
    float y; asm("ex2.approx.ftz.f32 %0, %1;" : "=f"(y) : "f"(x)); return y;
}
// pack {lo=lo_src, hi=hi_src} into f16x2
__device__ __forceinline__ uint32_t cvtf16x2(float hi_src, float lo_src){
    uint32_t d;
    asm("cvt.rn.f16x2.f32 %0, %1, %2;" : "=r"(d) : "f"(hi_src), "f"(lo_src));
    return d;
}
__device__ __forceinline__ uint32_t h2ex2(uint32_t x){
    uint32_t d;
    asm("ex2.approx.f16x2 %0, %1;" : "=r"(d) : "r"(x));
    return d;
}
__device__ __forceinline__ float2 h2tof2(uint32_t x){
    __half2 h = *reinterpret_cast<__half2*>(&x);
    return __half22float2(h);
}

// ---------------- prep: fp32 -> fp16 -------------------------------------------
__global__ __launch_bounds__(256) void cvt_kernel(
    const float* __restrict__ in, __half* __restrict__ out, int n4)
{
    int i = blockIdx.x * blockDim.x + threadIdx.x;
    if (i < n4){
        float4 v = reinterpret_cast<const float4*>(in)[i];
        uint2 u;
        u.x = pack2(v.x, v.y);
        u.y = pack2(v.z, v.w);
        reinterpret_cast<uint2*>(out)[i] = u;
    }
}

// ---------------- prep: concat qkv bias + log2e-premultiplied mask -------------
__global__ __launch_bounds__(256) void prep_kernel(
    const float* __restrict__ bq, const float* __restrict__ bk,
    const float* __restrict__ bv, const float* __restrict__ mask,
    float* __restrict__ bqkv, float* __restrict__ negm)
{
    int i = blockIdx.x * blockDim.x + threadIdx.x;
    if (i < NQKV)
        bqkv[i] = (i < Dv) ? bq[i] : (i < 2*Dv) ? bk[i - Dv] : bv[i - 2*Dv];
    int j = i - NQKV;
    if (j >= 0 && j < Bv*Sv)
        negm[j] = -1.4426950408889634e9f * mask[j];
}

// ---------------- prep: all weight transposes ----------------------------------
__device__ __forceinline__ void transp_tile(
    const float* __restrict__ in, __half* __restrict__ out,
    int R, int C, int bx, int by)
{
    __shared__ float t[32][33];
    int tx = threadIdx.x, ty = threadIdx.y;         // block (32,8)
    #pragma unroll
    for (int j = 0; j < 32; j += 8)
        t[ty + j][tx] = in[(size_t)(by + ty + j) * C + bx + tx];
    __syncthreads();
    #pragma unroll
    for (int j = 0; j < 32; j += 8)
        out[(size_t)(bx + ty + j) * R + by + tx] = __float2half_rn(t[tx][ty + j]);
}

__global__ __launch_bounds__(256) void transp_all(
    const float* wq, const float* wk, const float* wv, const float* wo,
    const float* w1, const float* w2,
    __half* wqkvT, __half* woT, __half* w1T, __half* w2T)
{
    int bid = blockIdx.x;   // 0..767
    if (bid < 256){
        int m = bid >> 6, t = bid & 63;
        int bx = (t & 7) * 32, by = (t >> 3) * 32;
        const float* in  = (m==0)? wq : (m==1)? wk : (m==2)? wv : wo;
        __half*      outp= (m==3)? woT : wqkvT + (size_t)m * Dv * Dv;
        transp_tile(in, outp, Dv, Dv, bx, by);
    } else if (bid < 512){
        int t = bid - 256;
        int bx = (t & 31) * 32, by = (t >> 5) * 32;
        transp_tile(w1, w1T, Dv, DFFv, bx, by);
    } else {
        int t = bid - 512;
        int bx = (t & 7) * 32, by = (t >> 3) * 32;
        transp_tile(w2, w2T, DFFv, Dv, bx, by);
    }
}

// ---------------- fp16 GEMM: 3-stage ring, LDS.64 k-interleaved (proven R7) -----
#define GST 80
#define GEMM_SMEM_BYTES ((3*128*GST + 3*64*GST)*2)

template<bool RELU, bool HOUT>
__global__ __launch_bounds__(256) void gemm_h(
    const __half* __restrict__ A, const __half* __restrict__ Bt,
    const float* __restrict__ bias, const float* __restrict__ res,
    float* __restrict__ Yf, __half* __restrict__ Yh, int M, int N, int K)
{
    extern __shared__ char gsm[];
    __half* As = reinterpret_cast<__half*>(gsm);          // 3 stages [128][GST]
    __half* Bs = As + 3*128*GST;                          // 3 stages [64][GST]

    const int tid  = threadIdx.x;
    const int lane = tid & 31;
    const int gid  = lane >> 2, tig = lane & 3;
    const int wid  = tid >> 5;
    const int wm   = wid >> 1, wn = wid & 1;
    const int bm   = blockIdx.y * 128, bn = blockIdx.x * 64;

    float acc[2][4][4];
    #pragma unroll
    for (int i = 0; i < 2; i++)
        #pragma unroll
        for (int j = 0; j < 4; j++)
            #pragma unroll
            for (int k = 0; k < 4; k++) acc[i][j][k] = 0.f;

    const int ar  = tid >> 2;           // A row 0..63 (+64)
    const int ac  = (tid & 3) * 8;      // A col chunk (16B)
    const int bn_ = tid >> 2;           // B n row 0..63
    const int bc  = (tid & 3) * 8;      // B k chunk

    auto stage = [&](int k0, int st){
        __half* Ad = As + st*128*GST;
        __half* Bd = Bs + st*64*GST;
        #pragma unroll
        for (int ir = 0; ir < 2; ir++){
            int r = ar + ir * 64;
            cpa16(&Ad[r * GST + ac], A + (size_t)(bm + r) * K + k0 + ac);
        }
        cpa16(&Bd[bn_ * GST + bc], Bt + (size_t)(bn + bn_) * K + k0 + bc);
        cpa_commit();
    };

    const int KIT = K >> 5;
    stage(0, 0);
    stage(32, 1);

    for (int it = 0; it < KIT; it++){
        if (it + 1 < KIT) cpa_wait<1>(); else cpa_wait<0>();
        __syncthreads();
        if (it + 2 < KIT) stage((it + 2) * 32, (it + 2) % 3);

        const __half* Ab = As + (it % 3)*128*GST;
        const __half* Bb = Bs + (it % 3)*64*GST;
        #pragma unroll
        for (int ks = 0; ks < 2; ks++){
            const int kc = ks * 16 + 4 * tig;      // interleaved k chunk
            uint32_t af[2][4];
            #pragma unroll
            for (int mt = 0; mt < 2; mt++){
                int r0 = wm*32 + mt*16 + gid;
                uint2 lo = lds64(&Ab[ r0      * GST + kc]);
                uint2 hi = lds64(&Ab[(r0 + 8) * GST + kc]);
                af[mt][0] = lo.x; af[mt][2] = lo.y;
                af[mt][1] = hi.x; af[mt][3] = hi.y;
            }
            #pragma unroll
            for (int nt = 0; nt < 4; nt++){
                uint2 bv = lds64(&Bb[(wn*32 + nt*8 + gid) * GST + kc]);
                #pragma unroll
                for (int mt = 0; mt < 2; mt++)
                    mma_f16(acc[mt][nt], af[mt], bv.x, bv.y);
            }
        }
    }

    #pragma unroll
    for (int mt = 0; mt < 2; mt++){
        #pragma unroll
        for (int nt = 0; nt < 4; nt++){
            int col = bn + wn * 32 + nt * 8 + 2 * tig;
            float b0 = bias[col], b1 = bias[col + 1];
            int r0 = bm + wm * 32 + mt * 16 + gid;
            #pragma unroll
            for (int hf = 0; hf < 2; hf++){
                int row = r0 + hf * 8;
                float v0 = acc[mt][nt][hf*2+0] + b0;
                float v1 = acc[mt][nt][hf*2+1] + b1;
                if (res){
                    v0 += res[(size_t)row * N + col];
                    v1 += res[(size_t)row * N + col + 1];
                }
                if (RELU){ v0 = fmaxf(v0, 0.f); v1 = fmaxf(v1, 0.f); }
                if (HOUT){
                    __half2 hv = __floats2half2_rn(v0, v1);
                    *reinterpret_cast<__half2*>(Yh + (size_t)row * N + col) = hv;
                } else {
                    *reinterpret_cast<float2*>(Yf + (size_t)row * N + col) = make_float2(v0, v1);
                }
            }
        }
    }
}

// ---------------- flash attention: log2 softmax in f16x2, permuted sVT ---------
// CTA: 256 queries of one (b,h); 8 warps x 32 q-rows; 32 key-tiles of 128.
// sVT key-permuted within 16-key groups so PV (b0,b1) is one LDS.64.
// exp via ex2.approx.f16x2 -> result IS the PV A-fragment.
// Masks dedup'd: one broadcast float2 per nt shared by both m-tiles.
#define QST  80
#define KST2 80
#define VST  72
#define VTST 136
#define NT_TILES (Sv/128)
#define QROWS 256
#define ATTN_SMEM_BYTES ((QROWS*QST + 2*128*KST2 + 2*128*VST + 64*VTST)*2 + 2*128*4)

__global__ __launch_bounds__(256, 1) void attn_h(
    const __half* __restrict__ QKV, const float* __restrict__ negm,
    __half* __restrict__ O)
{
    extern __shared__ char smem_raw[];
    __half* sQ  = reinterpret_cast<__half*>(smem_raw);
    __half* sK0 = sQ  + QROWS*QST;
    __half* sK1 = sK0 + 128*KST2;
    __half* sV0 = sK1 + 128*KST2;
    __half* sV1 = sV0 + 128*VST;
    __half* sVT = sV1 + 128*VST;
    float* sMask0 = reinterpret_cast<float*>(sVT + 64*VTST);
    float* sMask1 = sMask0 + 128;

    const int tid = threadIdx.x, lane = tid & 31, wid = tid >> 5;
    const int gid = lane >> 2, tig = lane & 3;
    const int m0  = wid * 32;
    const int b   = blockIdx.y >> 2, h = blockIdx.y & 3;
    const int q0  = blockIdx.x * QROWS;
    const __half* Qb = QKV + (size_t)b*Sv*NQKV + (size_t)h*DEP;
    const __half* Kb = Qb + Dv;
    const __half* Vb = Qb + 2*Dv;
    const float*  Mb = negm + (size_t)b*Sv;

    const int sr  = tid >> 2;            // staging row 0..63
    const int sc  = (tid & 3) * 16;      // staging col (two 16B chunks)

    auto stageKVM = [&](int kt, __half* dK, __half* dV, float* dM){
        const int kbase = kt * 128;
        #pragma unroll
        for (int ir = 0; ir < 2; ir++){
            int row = sr + ir * 64;
            const __half* ks_ = Kb + (size_t)(kbase + row) * NQKV + sc;
            cpa16(&dK[row*KST2 + sc    ], ks_);
            cpa16(&dK[row*KST2 + sc + 8], ks_ + 8);
            const __half* vs_ = Vb + (size_t)(kbase + row) * NQKV + sc;
            cpa16(&dV[row*VST + sc    ], vs_);
            cpa16(&dV[row*VST + sc + 8], vs_ + 8);
        }
        if (tid < 32) cpa16(&dM[tid*4], Mb + kbase + tid*4);
    };

    // prologue: Q (256 rows) + tile0
    {
        #pragma unroll
        for (int ir = 0; ir < 4; ir++){
            int row = sr + ir * 64;
            const __half* src = Qb + (size_t)(q0 + row) * NQKV + sc;
            cpa16(&sQ[row*QST + sc    ], src);
            cpa16(&sQ[row*QST + sc + 8], src + 8);
        }
        stageKVM(0, sK0, sV0, sMask0);
        cpa_commit();
    }
    cpa_wait<0>();
    __syncthreads();

    // Q fragments in registers, k-interleaved layout (LDS.64)
    uint32_t qf[2][4][4];
    #pragma unroll
    for (int mt = 0; mt < 2; mt++){
        #pragma unroll
        for (int kd = 0; kd < 4; kd++){
            int r0 = m0 + mt*16 + gid;
            uint2 lo = lds64(&sQ[ r0      * QST + kd*16 + 4*tig]);
            uint2 hi = lds64(&sQ[(r0 + 8) * QST + kd*16 + 4*tig]);
            qf[mt][kd][0] = lo.x; qf[mt][kd][2] = lo.y;
            qf[mt][kd][1] = hi.x; qf[mt][kd][3] = hi.y;
        }
    }

    float o[2][8][4];
    #pragma unroll
    for (int mt = 0; mt < 2; mt++)
        #pragma unroll
        for (int i = 0; i < 8; i++){
            o[mt][i][0]=o[mt][i][1]=o[mt][i][2]=o[mt][i][3]=0.f;
        }
    float mrow[2][2] = {{-1e30f,-1e30f},{-1e30f,-1e30f}};
    float lrow[2][2] = {{0.f,0.f},{0.f,0.f}};

    const int vkp = tid & 63;            // V-transpose key pair index
    const int vdb = (tid >> 6) * 8;      // V-transpose d base
    const int vgrp = vkp >> 3, vt = vkp & 7;
    const int vslot = (vt < 4) ? (2*vt) : (2*(vt-4) + 1);
    const int vhoff = vgrp*16 + vslot*2;  // half offset of this pair in sVT row

    for (int kt = 0; kt < NT_TILES; kt++){
        const int buf = kt & 1;
        __half* cK = buf ? sK1 : sK0;
        __half* cV = buf ? sV1 : sV0;
        float*  cM = buf ? sMask1 : sMask0;
        const bool nxt = (kt + 1 < NT_TILES);
        if (nxt){
            stageKVM(kt + 1, buf ? sK0 : sK1, buf ? sV0 : sV1,
                     buf ? sMask0 : sMask1);
            cpa_commit();
        }

        // transpose V: cV[key][d] -> sVT[d][perm(key)]
        #pragma unroll
        for (int it = 0; it < 2; it++){
            int d0 = vdb + it * 32;
            uint4 va = *reinterpret_cast<const uint4*>(&cV[(2*vkp    )*VST + d0]);
            uint4 vb = *reinterpret_cast<const uint4*>(&cV[(2*vkp + 1)*VST + d0]);
            const __half* ha = reinterpret_cast<const __half*>(&va);
            const __half* hb = reinterpret_cast<const __half*>(&vb);
            #pragma unroll
            for (int j = 0; j < 8; j++){
                __half2 pr = __halves2half2(ha[j], hb[j]);
                *reinterpret_cast<uint32_t*>(&sVT[(d0+j)*VTST + vhoff]) =
                    *reinterpret_cast<uint32_t*>(&pr);
            }
        }

        #pragma unroll
        for (int hh2 = 0; hh2 < 2; hh2++){
            const int kh0 = hh2 * 64;
            // ---- S = Q @ K^T over 64 keys, shared B-fragments ----
            float p[2][8][4];
            #pragma unroll
            for (int mt = 0; mt < 2; mt++)
                #pragma unroll
                for (int nt = 0; nt < 8; nt++){
                    p[mt][nt][0]=p[mt][nt][1]=p[mt][nt][2]=p[mt][nt][3]=0.f;
                }
            #pragma unroll
            for (int kd = 0; kd < 4; kd++){
                #pragma unroll
                for (int nt = 0; nt < 8; nt++){
                    uint2 bv = lds64(&cK[(kh0 + nt*8 + gid)*KST2 + kd*16 + 4*tig]);
                    mma_f16(p[0][nt], qf[0][kd], bv.x, bv.y);
                    mma_f16(p[1][nt], qf[1][kd], bv.x, bv.y);
                }
            }
            if (hh2 == 0) __syncthreads();   // sVT + masks visible before use

            // ---- masks: one broadcast float2 per nt, shared by both mt ----
            float2 mnt[8];
            #pragma unroll
            for (int nt = 0; nt < 8; nt++)
                mnt[nt] = *reinterpret_cast<const float2*>(&cM[kh0 + nt*8 + 2*tig]);

            // ---- online softmax (log2 domain, f16x2 exp) per m-tile ----
            uint32_t pe[2][8][2];            // [mt][nt][{pair01, pair23}]
            #pragma unroll
            for (int mt = 0; mt < 2; mt++){
                float rmax[2] = {-1e30f, -1e30f};
                #pragma unroll
                for (int nt = 0; nt < 8; nt++){
                    p[mt][nt][0] = fmaf(p[mt][nt][0], S_LOG2E, mnt[nt].x);
                    p[mt][nt][1] = fmaf(p[mt][nt][1], S_LOG2E, mnt[nt].y);
                    p[mt][nt][2] = fmaf(p[mt][nt][2], S_LOG2E, mnt[nt].x);
                    p[mt][nt][3] = fmaf(p[mt][nt][3], S_LOG2E, mnt[nt].y);
                    rmax[0] = fmaxf(rmax[0], fmaxf(p[mt][nt][0], p[mt][nt][1]));
                    rmax[1] = fmaxf(rmax[1], fmaxf(p[mt][nt][2], p[mt][nt][3]));
                }
                #pragma unroll
                for (int hh = 0; hh < 2; hh++){
                    rmax[hh] = fmaxf(rmax[hh], __shfl_xor_sync(0xffffffffu, rmax[hh], 1));
                    rmax[hh] = fmaxf(rmax[hh], __shfl_xor_sync(0xffffffffu, rmax[hh], 2));
                }
                float mnew[2], alpha[2], rsum[2];
                #pragma unroll
                for (int hh = 0; hh < 2; hh++){
                    mnew[hh]  = fmaxf(mrow[mt][hh], rmax[hh]);
                    alpha[hh] = ex2(mrow[mt][hh] - mnew[hh]);
                    rsum[hh]  = 0.f;
                }
                #pragma unroll
                for (int nt = 0; nt < 8; nt++){
                    float t0 = p[mt][nt][0] - mnew[0];
                    float t1 = p[mt][nt][1] - mnew[0];
                    float t2 = p[mt][nt][2] - mnew[1];
                    float t3 = p[mt][nt][3] - mnew[1];
                    uint32_t e01 = h2ex2(cvtf16x2(t1, t0));   // {lo e0, hi e1}
                    uint32_t e23 = h2ex2(cvtf16x2(t3, t2));   // {lo e2, hi e3}
                    pe[mt][nt][0] = e01;
                    pe[mt][nt][1] = e23;
                    float2 f01 = h2tof2(e01);
                    float2 f23 = h2tof2(e23);
                    rsum[0] += f01.x + f01.y;
                    rsum[1] += f23.x + f23.y;
                }
                #pragma unroll
                for (int hh = 0; hh < 2; hh++){
                    rsum[hh] += __shfl_xor_sync(0xffffffffu, rsum[hh], 1);
                    rsum[hh] += __shfl_xor_sync(0xffffffffu, rsum[hh], 2);
                    lrow[mt][hh] = lrow[mt][hh] * alpha[hh] + rsum[hh];
                    mrow[mt][hh] = mnew[hh];
                }
                #pragma unroll
                for (int nt = 0; nt < 8; nt++){
                    o[mt][nt][0] *= alpha[0]; o[mt][nt][1] *= alpha[0];
                    o[mt][nt][2] *= alpha[1]; o[mt][nt][3] *= alpha[1];
                }
            }

            // ---- O += P @ V; pe IS the A-fragment, permuted sVT -> one LDS.64 --
            #pragma unroll
            for (int ks = 0; ks < 4; ks++){
                uint32_t ap[2][4];
                #pragma unroll
                for (int mt = 0; mt < 2; mt++){
                    ap[mt][0] = pe[mt][2*ks  ][0];
                    ap[mt][1] = pe[mt][2*ks  ][1];
                    ap[mt][2] = pe[mt][2*ks+1][0];
                    ap[mt][3] = pe[mt][2*ks+1][1];
                }
                #pragma unroll
                for (int nt = 0; nt < 8; nt++){
                    uint2 bv = lds64(&sVT[(nt*8 + gid)*VTST + kh0 + ks*16 + 4*tig]);
                    mma_f16(o[0][nt], ap[0], bv.x, bv.y);
                    mma_f16(o[1][nt], ap[1], bv.x, bv.y);
                }
            }
        }
        if (nxt) cpa_wait<0>();
        __syncthreads();
    }

    #pragma unroll
    for (int mt = 0; mt < 2; mt++){
        float inv0 = 1.f / lrow[mt][0], inv1 = 1.f / lrow[mt][1];
        #pragma unroll
        for (int nt = 0; nt < 8; nt++){
            int col  = h * DEP + nt * 8 + 2 * tig;
            int row0 = q0 + m0 + mt*16 + gid;
            __half2 h0 = __floats2half2_rn(o[mt][nt][0]*inv0, o[mt][nt][1]*inv0);
            __half2 h1 = __floats2half2_rn(o[mt][nt][2]*inv1, o[mt][nt][3]*inv1);
            *reinterpret_cast<__half2*>(O + (size_t)(b*Sv + row0    )*Dv + col) = h0;
            *reinterpret_cast<__half2*>(O + (size_t)(b*Sv + row0 + 8)*Dv + col) = h1;
        }
    }
}

// ---------------- LayerNorm: warp per row --------------------------------------
__global__ __launch_bounds__(256) void ln_kernel(
    const float* __restrict__ in, float* __restrict__ out, __half* __restrict__ outh,
    const float* __restrict__ g, const float* __restrict__ bt,
    int N, float eps)
{
    const int lane = threadIdx.x & 31;
    const int row  = blockIdx.x * 8 + (threadIdx.x >> 5);
    const int nch  = N >> 7;
    const float* x = in + (size_t)row * N;

    float4 v[8];
    float s = 0.f;
    for (int j = 0; j < nch; j++){
        v[j] = *reinterpret_cast<const float4*>(x + j*128 + lane*4);
        s += v[j].x + v[j].y + v[j].z + v[j].w;
    }
    #pragma unroll
    for (int o = 16; o; o >>= 1) s += __shfl_xor_sync(0xffffffffu, s, o);
    float mu = s / N;
    float var = 0.f;
    for (int j = 0; j < nch; j++){
        float dx = v[j].x-mu, dy = v[j].y-mu, dz = v[j].z-mu, dw = v[j].w-mu;
        var += dx*dx + dy*dy + dz*dz + dw*dw;
    }
    #pragma unroll
    for (int o = 16; o; o >>= 1) var += __shfl_xor_sync(0xffffffffu, var, o);
    float rstd = rsqrtf(var / N + eps);

    for (int j = 0; j < nch; j++){
        int c = j*128 + lane*4;
        float4 gg = *reinterpret_cast<const float4*>(g  + c);
        float4 bb = *reinterpret_cast<const float4*>(bt + c);
        float y0 = (v[j].x - mu) * rstd * gg.x + bb.x;
        float y1 = (v[j].y - mu) * rstd * gg.y + bb.y;
        float y2 = (v[j].z - mu) * rstd * gg.z + bb.z;
        float y3 = (v[j].w - mu) * rstd * gg.w + bb.w;
        if (out)
            *reinterpret_cast<float4*>(out + (size_t)row * N + c) =
                make_float4(y0, y1, y2, y3);
        if (outh){
            uint2 u;
            u.x = pack2(y0, y1);
            u.y = pack2(y2, y3);
            *reinterpret_cast<uint2*>(outh + (size_t)row * N + c) = u;
        }
    }
}

// ---------------- launch --------------------------------------------------------
extern "C" void kernel_launch(void* const* d_in, const int* in_sizes, int n_in,
                              void* d_out, int out_size)
{
    (void)in_sizes; (void)n_in; (void)out_size;
    const float* x    = (const float*)d_in[0];
    const float* mask = (const float*)d_in[1];
    const float* wq   = (const float*)d_in[2];
    const float* bq   = (const float*)d_in[3];
    const float* wk   = (const float*)d_in[4];
    const float* bk   = (const float*)d_in[5];
    const float* wv   = (const float*)d_in[6];
    const float* bv   = (const float*)d_in[7];
    const float* wo   = (const float*)d_in[8];
    const float* bo   = (const float*)d_in[9];
    const float* w1   = (const float*)d_in[10];
    const float* b1   = (const float*)d_in[11];
    const float* lnffg= (const float*)d_in[12];
    const float* lnffb= (const float*)d_in[13];
    const float* w2   = (const float*)d_in[14];
    const float* b2   = (const float*)d_in[15];
    const float* ln1g = (const float*)d_in[16];
    const float* ln1b = (const float*)d_in[17];
    const float* ln2g = (const float*)d_in[18];
    const float* ln2b = (const float*)d_in[19];
    float* out = (float*)d_out;

    float  *X1, *Hb, *negm, *bqkv;
    __half *xh, *QKVh, *ctxh, *x1h, *hh;
    __half *wqkvT, *woT, *w1T, *w2T;
    cudaGetSymbolAddress((void**)&X1,    g_X1);
    cudaGetSymbolAddress((void**)&Hb,    g_H);
    cudaGetSymbolAddress((void**)&negm,  g_negm);
    cudaGetSymbolAddress((void**)&bqkv,  g_bqkv);
    cudaGetSymbolAddress((void**)&xh,    g_xh);
    cudaGetSymbolAddress((void**)&QKVh,  g_QKVh);
    cudaGetSymbolAddress((void**)&ctxh,  g_ctxh);
    cudaGetSymbolAddress((void**)&x1h,   g_x1h);
    cudaGetSymbolAddress((void**)&hh,    g_hh);
    cudaGetSymbolAddress((void**)&wqkvT, g_wqkvT);
    cudaGetSymbolAddress((void**)&woT,   g_woT);
    cudaGetSymbolAddress((void**)&w1T,   g_w1T);
    cudaGetSymbolAddress((void**)&w2T,   g_w2T);

    cudaFuncSetAttribute(attn_h, cudaFuncAttributeMaxDynamicSharedMemorySize,
                         ATTN_SMEM_BYTES);
    cudaFuncSetAttribute(gemm_h<false,true>,  cudaFuncAttributeMaxDynamicSharedMemorySize, GEMM_SMEM_BYTES);
    cudaFuncSetAttribute(gemm_h<false,false>, cudaFuncAttributeMaxDynamicSharedMemorySize, GEMM_SMEM_BYTES);
    cudaFuncSetAttribute(gemm_h<true,false>,  cudaFuncAttributeMaxDynamicSharedMemorySize, GEMM_SMEM_BYTES);

    const dim3 blk(256);
    const dim3 gQKV(NQKV/64, MTOK/128);
    const dim3 gP(Dv/64,    MTOK/128);
    const dim3 gF(DFFv/64,  MTOK/128);

    // prep
    cvt_kernel<<<(MTOK*Dv/4 + 255)/256, blk>>>(x, xh, MTOK*Dv/4);
    prep_kernel<<<(NQKV + Bv*Sv + 255)/256, blk>>>(bq, bk, bv, mask, bqkv, negm);
    transp_all<<<768, dim3(32,8)>>>(wq, wk, wv, wo, w1, w2,
                                    wqkvT, woT, w1T, w2T);
    // fused QKV projection (half out, row stride 768)
    gemm_h<false,true><<<gQKV, blk, GEMM_SMEM_BYTES>>>(xh, wqkvT, bqkv, nullptr,
                                                       nullptr, QKVh, MTOK, NQKV, Dv);
    // attention
    attn_h<<<dim3(Sv/QROWS, Bv*Hv), blk, ATTN_SMEM_BYTES>>>(QKVh, negm, ctxh);
    // out-proj + residual, LN1
    gemm_h<false,false><<<gP, blk, GEMM_SMEM_BYTES>>>(ctxh, woT, bo, x, X1, nullptr,
                                                      MTOK, Dv, Dv);
    ln_kernel<<<MTOK/8, blk>>>(X1, X1, x1h, ln1g, ln1b, Dv, 1e-3f);
    // FFN1 + relu, LN_ff
    gemm_h<true,false><<<gF, blk, GEMM_SMEM_BYTES>>>(x1h, w1T, b1, nullptr, Hb, nullptr,
                                                     MTOK, DFFv, Dv);
    ln_kernel<<<MTOK/8, blk>>>(Hb, nullptr, hh, lnffg, lnffb, DFFv, 1e-6f);
    // FFN2 + residual, LN2
    gemm_h<false,false><<<gP, blk, GEMM_SMEM_BYTES>>>(hh, w2T, b2, X1, out, nullptr,
                                                      MTOK, Dv, DFFv);
    ln_kernel<<<MTOK/8, blk>>>(out, out, nullptr, ln2g, ln2b, Dv, 1e-3f);
}

// round 15
// speedup vs baseline: 1.0536x; 1.0215x over previous
#include <cuda_runtime.h>
#include <cuda_fp16.h>
#include <cstdint>
#include <cstddef>

#define Bv   4
#define Sv   4096
#define Dv   256
#define Hv   4
#define DEP  64
#define DFFv 1024
#define MTOK (Bv*Sv)
#define NQKV (3*Dv)
#define S_LOG2E 0.18033688011112042f   /* 0.125 * log2(e) */

// ---------------- scratch (device globals) ------------------------------------
__device__ float  g_X1[MTOK*Dv];
__device__ float  g_H [(size_t)MTOK*DFFv];
__device__ float  g_negm[Bv*Sv];
__device__ float  g_bqkv[NQKV];
__device__ __half g_xh   [MTOK*Dv];
__device__ __half g_QKVh [(size_t)MTOK*NQKV];
__device__ __half g_ctxh [MTOK*Dv];
__device__ __half g_x1h  [MTOK*Dv];
__device__ __half g_hh   [(size_t)MTOK*DFFv];
__device__ __half g_wqkvT[(size_t)NQKV*Dv];
__device__ __half g_woT[Dv*Dv];
__device__ __half g_w1T[(size_t)DFFv*Dv];
__device__ __half g_w2T[(size_t)Dv*DFFv];

// ---------------- helpers ------------------------------------------------------
__device__ __forceinline__ uint32_t sm32(const void* p){
    return (uint32_t)__cvta_generic_to_shared(p);
}
__device__ __forceinline__ void cpa16(void* s, const void* g){
    asm volatile("cp.async.cg.shared.global [%0], [%1], 16;"
                 :: "r"(sm32(s)), "l"(g));
}
__device__ __forceinline__ void cpa_commit(){
    asm volatile("cp.async.commit_group;");
}
template<int N> __device__ __forceinline__ void cpa_wait(){
    asm volatile("cp.async.wait_group %0;" :: "n"(N));
}
__device__ __forceinline__ void mma_f16(float* c, const uint32_t* a,
                                        uint32_t b0, uint32_t b1){
    asm volatile(
      "mma.sync.aligned.m16n8k16.row.col.f32.f16.f16.f32 "
      "{%0,%1,%2,%3},{%4,%5,%6,%7},{%8,%9},{%0,%1,%2,%3};\n"
      : "+f"(c[0]), "+f"(c[1]), "+f"(c[2]), "+f"(c[3])
      : "r"(a[0]), "r"(a[1]), "r"(a[2]), "r"(a[3]), "r"(b0), "r"(b1));
}
__device__ __forceinline__ uint32_t pack2(float a, float b){
    __half2 h = __floats2half2_rn(a, b);
    return *reinterpret_cast<uint32_t*>(&h);
}
__device__ __forceinline__ uint32_t lds32(const __half* p){
    return *reinterpret_cast<const uint32_t*>(p);
}
__device__ __forceinline__ uint2 lds64(const __half* p){
    return *reinterpret_cast<const uint2*>(p);
}
__device__ __forceinline__ float ex2(float x){
    float y; asm("ex2.approx.ftz.f32 %0, %1;" : "=f"(y) : "f"(x)); return y;
}
// pack {lo=lo_src, hi=hi_src} into f16x2
__device__ __forceinline__ uint32_t cvtf16x2(float hi_src, float lo_src){
    uint32_t d;
    asm("cvt.rn.f16x2.f32 %0, %1, %2;" : "=r"(d) : "f"(hi_src), "f"(lo_src));
    return d;
}
__device__ __forceinline__ uint32_t h2ex2(uint32_t x){
    uint32_t d;
    asm("ex2.approx.f16x2 %0, %1;" : "=r"(d) : "r"(x));
    return d;
}
__device__ __forceinline__ float2 h2tof2(uint32_t x){
    __half2 h = *reinterpret_cast<__half2*>(&x);
    return __half22float2(h);
}

// ---------------- prep: fp32 -> fp16 -------------------------------------------
__global__ __launch_bounds__(256) void cvt_kernel(
    const float* __restrict__ in, __half* __restrict__ out, int n4)
{
    int i = blockIdx.x * blockDim.x + threadIdx.x;
    if (i < n4){
        float4 v = reinterpret_cast<const float4*>(in)[i];
        uint2 u;
        u.x = pack2(v.x, v.y);
        u.y = pack2(v.z, v.w);
        reinterpret_cast<uint2*>(out)[i] = u;
    }
}

// ---------------- prep: concat qkv bias + log2e-premultiplied mask -------------
__global__ __launch_bounds__(256) void prep_kernel(
    const float* __restrict__ bq, const float* __restrict__ bk,
    const float* __restrict__ bv, const float* __restrict__ mask,
    float* __restrict__ bqkv, float* __restrict__ negm)
{
    int i = blockIdx.x * blockDim.x + threadIdx.x;
    if (i < NQKV)
        bqkv[i] = (i < Dv) ? bq[i] : (i < 2*Dv) ? bk[i - Dv] : bv[i - 2*Dv];
    int j = i - NQKV;
    if (j >= 0 && j < Bv*Sv)
        negm[j] = -1.4426950408889634e9f * mask[j];
}

// ---------------- prep: all weight transposes ----------------------------------
__device__ __forceinline__ void transp_tile(
    const float* __restrict__ in, __half* __restrict__ out,
    int R, int C, int bx, int by)
{
    __shared__ float t[32][33];
    int tx = threadIdx.x, ty = threadIdx.y;         // block (32,8)
    #pragma unroll
    for (int j = 0; j < 32; j += 8)
        t[ty + j][tx] = in[(size_t)(by + ty + j) * C + bx + tx];
    __syncthreads();
    #pragma unroll
    for (int j = 0; j < 32; j += 8)
        out[(size_t)(bx + ty + j) * R + by + tx] = __float2half_rn(t[tx][ty + j]);
}

__global__ __launch_bounds__(256) void transp_all(
    const float* wq, const float* wk, const float* wv, const float* wo,
    const float* w1, const float* w2,
    __half* wqkvT, __half* woT, __half* w1T, __half* w2T)
{
    int bid = blockIdx.x;   // 0..767
    if (bid < 256){
        int m = bid >> 6, t = bid & 63;
        int bx = (t & 7) * 32, by = (t >> 3) * 32;
        const float* in  = (m==0)? wq : (m==1)? wk : (m==2)? wv : wo;
        __half*      outp= (m==3)? woT : wqkvT + (size_t)m * Dv * Dv;
        transp_tile(in, outp, Dv, Dv, bx, by);
    } else if (bid < 512){
        int t = bid - 256;
        int bx = (t & 31) * 32, by = (t >> 5) * 32;
        transp_tile(w1, w1T, Dv, DFFv, bx, by);
    } else {
        int t = bid - 512;
        int bx = (t & 7) * 32, by = (t >> 3) * 32;
        transp_tile(w2, w2T, DFFv, Dv, bx, by);
    }
}

// ---------------- fp16 GEMM: 3-stage ring, LDS.64 k-interleaved ----------------
// GST=48 (rows hold 32 halves + 16 pad): smem 55.3KB -> 3 CTAs/SM.
// Bank check: fragment rows stride 96B = 24 banks; per-phase row bases
// {0,24,16,8} + 2*tig -> conflict-free.
#define GST 48
#define GEMM_SMEM_BYTES ((3*128*GST + 3*64*GST)*2)

template<bool RELU, bool HOUT>
__global__ __launch_bounds__(256) void gemm_h(
    const __half* __restrict__ A, const __half* __restrict__ Bt,
    const float* __restrict__ bias, const float* __restrict__ res,
    float* __restrict__ Yf, __half* __restrict__ Yh, int M, int N, int K)
{
    extern __shared__ char gsm[];
    __half* As = reinterpret_cast<__half*>(gsm);          // 3 stages [128][GST]
    __half* Bs = As + 3*128*GST;                          // 3 stages [64][GST]

    const int tid  = threadIdx.x;
    const int lane = tid & 31;
    const int gid  = lane >> 2, tig = lane & 3;
    const int wid  = tid >> 5;
    const int wm   = wid >> 1, wn = wid & 1;
    const int bm   = blockIdx.y * 128, bn = blockIdx.x * 64;

    float acc[2][4][4];
    #pragma unroll
    for (int i = 0; i < 2; i++)
        #pragma unroll
        for (int j = 0; j < 4; j++)
            #pragma unroll
            for (int k = 0; k < 4; k++) acc[i][j][k] = 0.f;

    const int ar  = tid >> 2;           // A row 0..63 (+64)
    const int ac  = (tid & 3) * 8;      // A col chunk (16B)
    const int bn_ = tid >> 2;           // B n row 0..63
    const int bc  = (tid & 3) * 8;      // B k chunk

    auto stage = [&](int k0, int st){
        __half* Ad = As + st*128*GST;
        __half* Bd = Bs + st*64*GST;
        #pragma unroll
        for (int ir = 0; ir < 2; ir++){
            int r = ar + ir * 64;
            cpa16(&Ad[r * GST + ac], A + (size_t)(bm + r) * K + k0 + ac);
        }
        cpa16(&Bd[bn_ * GST + bc], Bt + (size_t)(bn + bn_) * K + k0 + bc);
        cpa_commit();
    };

    const int KIT = K >> 5;
    stage(0, 0);
    stage(32, 1);

    for (int it = 0; it < KIT; it++){
        if (it + 1 < KIT) cpa_wait<1>(); else cpa_wait<0>();
        __syncthreads();
        if (it + 2 < KIT) stage((it + 2) * 32, (it + 2) % 3);

        const __half* Ab = As + (it % 3)*128*GST;
        const __half* Bb = Bs + (it % 3)*64*GST;
        #pragma unroll
        for (int ks = 0; ks < 2; ks++){
            const int kc = ks * 16 + 4 * tig;      // interleaved k chunk
            uint32_t af[2][4];
            #pragma unroll
            for (int mt = 0; mt < 2; mt++){
                int r0 = wm*32 + mt*16 + gid;
                uint2 lo = lds64(&Ab[ r0      * GST + kc]);
                uint2 hi = lds64(&Ab[(r0 + 8) * GST + kc]);
                af[mt][0] = lo.x; af[mt][2] = lo.y;
                af[mt][1] = hi.x; af[mt][3] = hi.y;
            }
            #pragma unroll
            for (int nt = 0; nt < 4; nt++){
                uint2 bv = lds64(&Bb[(wn*32 + nt*8 + gid) * GST + kc]);
                #pragma unroll
                for (int mt = 0; mt < 2; mt++)
                    mma_f16(acc[mt][nt], af[mt], bv.x, bv.y);
            }
        }
    }

    #pragma unroll
    for (int mt = 0; mt < 2; mt++){
        #pragma unroll
        for (int nt = 0; nt < 4; nt++){
            int col = bn + wn * 32 + nt * 8 + 2 * tig;
            float b0 = bias[col], b1 = bias[col + 1];
            int r0 = bm + wm * 32 + mt * 16 + gid;
            #pragma unroll
            for (int hf = 0; hf < 2; hf++){
                int row = r0 + hf * 8;
                float v0 = acc[mt][nt][hf*2+0] + b0;
                float v1 = acc[mt][nt][hf*2+1] + b1;
                if (res){
                    v0 += res[(size_t)row * N + col];
                    v1 += res[(size_t)row * N + col + 1];
                }
                if (RELU){ v0 = fmaxf(v0, 0.f); v1 = fmaxf(v1, 0.f); }
                if (HOUT){
                    __half2 hv = __floats2half2_rn(v0, v1);
                    *reinterpret_cast<__half2*>(Yh + (size_t)row * N + col) = hv;
                } else {
                    *reinterpret_cast<float2*>(Yf + (size_t)row * N + col) = make_float2(v0, v1);
                }
            }
        }
    }
}

// ---------------- flash attention (exact R12 best-measured body) ---------------
#define QST  80
#define KST2 80
#define VST  72
#define VTST 136
#define NT_TILES (Sv/128)
#define QROWS 256
#define ATTN_SMEM_BYTES ((QROWS*QST + 2*128*KST2 + 2*128*VST + 64*VTST)*2 + 2*128*4)

__global__ __launch_bounds__(256, 1) void attn_h(
    const __half* __restrict__ QKV, const float* __restrict__ negm,
    __half* __restrict__ O)
{
    extern __shared__ char smem_raw[];
    __half* sQ  = reinterpret_cast<__half*>(smem_raw);
    __half* sK0 = sQ  + QROWS*QST;
    __half* sK1 = sK0 + 128*KST2;
    __half* sV0 = sK1 + 128*KST2;
    __half* sV1 = sV0 + 128*VST;
    __half* sVT = sV1 + 128*VST;
    float* sMask0 = reinterpret_cast<float*>(sVT + 64*VTST);
    float* sMask1 = sMask0 + 128;

    const int tid = threadIdx.x, lane = tid & 31, wid = tid >> 5;
    const int gid = lane >> 2, tig = lane & 3;
    const int m0  = wid * 32;
    const int b   = blockIdx.y >> 2, h = blockIdx.y & 3;
    const int q0  = blockIdx.x * QROWS;
    const __half* Qb = QKV + (size_t)b*Sv*NQKV + (size_t)h*DEP;
    const __half* Kb = Qb + Dv;
    const __half* Vb = Qb + 2*Dv;
    const float*  Mb = negm + (size_t)b*Sv;

    const int sr  = tid >> 2;            // staging row 0..63
    const int sc  = (tid & 3) * 16;      // staging col (two 16B chunks)

    auto stageKVM = [&](int kt, __half* dK, __half* dV, float* dM){
        const int kbase = kt * 128;
        #pragma unroll
        for (int ir = 0; ir < 2; ir++){
            int row = sr + ir * 64;
            const __half* ks_ = Kb + (size_t)(kbase + row) * NQKV + sc;
            cpa16(&dK[row*KST2 + sc    ], ks_);
            cpa16(&dK[row*KST2 + sc + 8], ks_ + 8);
            const __half* vs_ = Vb + (size_t)(kbase + row) * NQKV + sc;
            cpa16(&dV[row*VST + sc    ], vs_);
            cpa16(&dV[row*VST + sc + 8], vs_ + 8);
        }
        if (tid < 32) cpa16(&dM[tid*4], Mb + kbase + tid*4);
    };

    // prologue: Q (256 rows) + tile0
    {
        #pragma unroll
        for (int ir = 0; ir < 4; ir++){
            int row = sr + ir * 64;
            const __half* src = Qb + (size_t)(q0 + row) * NQKV + sc;
            cpa16(&sQ[row*QST + sc    ], src);
            cpa16(&sQ[row*QST + sc + 8], src + 8);
        }
        stageKVM(0, sK0, sV0, sMask0);
        cpa_commit();
    }
    cpa_wait<0>();
    __syncthreads();

    // Q fragments in registers, k-interleaved layout (LDS.64)
    uint32_t qf[2][4][4];
    #pragma unroll
    for (int mt = 0; mt < 2; mt++){
        #pragma unroll
        for (int kd = 0; kd < 4; kd++){
            int r0 = m0 + mt*16 + gid;
            uint2 lo = lds64(&sQ[ r0      * QST + kd*16 + 4*tig]);
            uint2 hi = lds64(&sQ[(r0 + 8) * QST + kd*16 + 4*tig]);
            qf[mt][kd][0] = lo.x; qf[mt][kd][2] = lo.y;
            qf[mt][kd][1] = hi.x; qf[mt][kd][3] = hi.y;
        }
    }

    float o[2][8][4];
    #pragma unroll
    for (int mt = 0; mt < 2; mt++)
        #pragma unroll
        for (int i = 0; i < 8; i++){
            o[mt][i][0]=o[mt][i][1]=o[mt][i][2]=o[mt][i][3]=0.f;
        }
    float mrow[2][2] = {{-1e30f,-1e30f},{-1e30f,-1e30f}};
    float lrow[2][2] = {{0.f,0.f},{0.f,0.f}};

    const int vkp = tid & 63;            // V-transpose key pair index
    const int vdb = (tid >> 6) * 8;      // V-transpose d base
    const int vgrp = vkp >> 3, vt = vkp & 7;
    const int vslot = (vt < 4) ? (2*vt) : (2*(vt-4) + 1);
    const int vhoff = vgrp*16 + vslot*2;  // half offset of this pair in sVT row

    for (int kt = 0; kt < NT_TILES; kt++){
        const int buf = kt & 1;
        __half* cK = buf ? sK1 : sK0;
        __half* cV = buf ? sV1 : sV0;
        float*  cM = buf ? sMask1 : sMask0;
        const bool nxt = (kt + 1 < NT_TILES);
        if (nxt){
            stageKVM(kt + 1, buf ? sK0 : sK1, buf ? sV0 : sV1,
                     buf ? sMask0 : sMask1);
            cpa_commit();
        }

        // transpose V: cV[key][d] -> sVT[d][perm(key)]
        #pragma unroll
        for (int it = 0; it < 2; it++){
            int d0 = vdb + it * 32;
            uint4 va = *reinterpret_cast<const uint4*>(&cV[(2*vkp    )*VST + d0]);
            uint4 vb = *reinterpret_cast<const uint4*>(&cV[(2*vkp + 1)*VST + d0]);
            const __half* ha = reinterpret_cast<const __half*>(&va);
            const __half* hb = reinterpret_cast<const __half*>(&vb);
            #pragma unroll
            for (int j = 0; j < 8; j++){
                __half2 pr = __halves2half2(ha[j], hb[j]);
                *reinterpret_cast<uint32_t*>(&sVT[(d0+j)*VTST + vhoff]) =
                    *reinterpret_cast<uint32_t*>(&pr);
            }
        }

        #pragma unroll
        for (int hh2 = 0; hh2 < 2; hh2++){
            const int kh0 = hh2 * 64;
            // ---- S = Q @ K^T over 64 keys, shared B-fragments ----
            float p[2][8][4];
            #pragma unroll
            for (int mt = 0; mt < 2; mt++)
                #pragma unroll
                for (int nt = 0; nt < 8; nt++){
                    p[mt][nt][0]=p[mt][nt][1]=p[mt][nt][2]=p[mt][nt][3]=0.f;
                }
            #pragma unroll
            for (int kd = 0; kd < 4; kd++){
                #pragma unroll
                for (int nt = 0; nt < 8; nt++){
                    uint2 bv = lds64(&cK[(kh0 + nt*8 + gid)*KST2 + kd*16 + 4*tig]);
                    mma_f16(p[0][nt], qf[0][kd], bv.x, bv.y);
                    mma_f16(p[1][nt], qf[1][kd], bv.x, bv.y);
                }
            }
            if (hh2 == 0) __syncthreads();   // sVT + masks visible before use

            // ---- online softmax (log2 domain, f16x2 exp) per m-tile ----
            uint32_t pe[2][8][2];            // [mt][nt][{pair01, pair23}]
            #pragma unroll
            for (int mt = 0; mt < 2; mt++){
                float rmax[2] = {-1e30f, -1e30f};
                #pragma unroll
                for (int nt = 0; nt < 8; nt++){
                    #pragma unroll
                    for (int j = 0; j < 4; j++){
                        int key = kh0 + nt*8 + 2*tig + (j & 1);
                        float s = fmaf(p[mt][nt][j], S_LOG2E, cM[key]);
                        p[mt][nt][j] = s;
                        rmax[j>>1] = fmaxf(rmax[j>>1], s);
                    }
                }
                #pragma unroll
                for (int hh = 0; hh < 2; hh++){
                    rmax[hh] = fmaxf(rmax[hh], __shfl_xor_sync(0xffffffffu, rmax[hh], 1));
                    rmax[hh] = fmaxf(rmax[hh], __shfl_xor_sync(0xffffffffu, rmax[hh], 2));
                }
                float mnew[2], alpha[2], rsum[2];
                #pragma unroll
                for (int hh = 0; hh < 2; hh++){
                    mnew[hh]  = fmaxf(mrow[mt][hh], rmax[hh]);
                    alpha[hh] = ex2(mrow[mt][hh] - mnew[hh]);
                    rsum[hh]  = 0.f;
                }
                #pragma unroll
                for (int nt = 0; nt < 8; nt++){
                    float t0 = p[mt][nt][0] - mnew[0];
                    float t1 = p[mt][nt][1] - mnew[0];
                    float t2 = p[mt][nt][2] - mnew[1];
                    float t3 = p[mt][nt][3] - mnew[1];
                    uint32_t e01 = h2ex2(cvtf16x2(t1, t0));   // {lo e0, hi e1}
                    uint32_t e23 = h2ex2(cvtf16x2(t3, t2));   // {lo e2, hi e3}
                    pe[mt][nt][0] = e01;
                    pe[mt][nt][1] = e23;
                    float2 f01 = h2tof2(e01);
                    float2 f23 = h2tof2(e23);
                    rsum[0] += f01.x + f01.y;
                    rsum[1] += f23.x + f23.y;
                }
                #pragma unroll
                for (int hh = 0; hh < 2; hh++){
                    rsum[hh] += __shfl_xor_sync(0xffffffffu, rsum[hh], 1);
                    rsum[hh] += __shfl_xor_sync(0xffffffffu, rsum[hh], 2);
                    lrow[mt][hh] = lrow[mt][hh] * alpha[hh] + rsum[hh];
                    mrow[mt][hh] = mnew[hh];
                }
                #pragma unroll
                for (int nt = 0; nt < 8; nt++){
                    o[mt][nt][0] *= alpha[0]; o[mt][nt][1] *= alpha[0];
                    o[mt][nt][2] *= alpha[1]; o[mt][nt][3] *= alpha[1];
                }
            }

            // ---- O += P @ V; pe IS the A-fragment, permuted sVT -> one LDS.64 --
            #pragma unroll
            for (int ks = 0; ks < 4; ks++){
                uint32_t ap[2][4];
                #pragma unroll
                for (int mt = 0; mt < 2; mt++){
                    ap[mt][0] = pe[mt][2*ks  ][0];
                    ap[mt][1] = pe[mt][2*ks  ][1];
                    ap[mt][2] = pe[mt][2*ks+1][0];
                    ap[mt][3] = pe[mt][2*ks+1][1];
                }
                #pragma unroll
                for (int nt = 0; nt < 8; nt++){
                    uint2 bv = lds64(&sVT[(nt*8 + gid)*VTST + kh0 + ks*16 + 4*tig]);
                    mma_f16(o[0][nt], ap[0], bv.x, bv.y);
                    mma_f16(o[1][nt], ap[1], bv.x, bv.y);
                }
            }
        }
        if (nxt) cpa_wait<0>();
        __syncthreads();
    }

    #pragma unroll
    for (int mt = 0; mt < 2; mt++){
        float inv0 = 1.f / lrow[mt][0], inv1 = 1.f / lrow[mt][1];
        #pragma unroll
        for (int nt = 0; nt < 8; nt++){
            int col  = h * DEP + nt * 8 + 2 * tig;
            int row0 = q0 + m0 + mt*16 + gid;
            __half2 h0 = __floats2half2_rn(o[mt][nt][0]*inv0, o[mt][nt][1]*inv0);
            __half2 h1 = __floats2half2_rn(o[mt][nt][2]*inv1, o[mt][nt][3]*inv1);
            *reinterpret_cast<__half2*>(O + (size_t)(b*Sv + row0    )*Dv + col) = h0;
            *reinterpret_cast<__half2*>(O + (size_t)(b*Sv + row0 + 8)*Dv + col) = h1;
        }
    }
}

// ---------------- LayerNorm: warp per row --------------------------------------
__global__ __launch_bounds__(256) void ln_kernel(
    const float* __restrict__ in, float* __restrict__ out, __half* __restrict__ outh,
    const float* __restrict__ g, const float* __restrict__ bt,
    int N, float eps)
{
    const int lane = threadIdx.x & 31;
    const int row  = blockIdx.x * 8 + (threadIdx.x >> 5);
    const int nch  = N >> 7;
    const float* x = in + (size_t)row * N;

    float4 v[8];
    float s = 0.f;
    for (int j = 0; j < nch; j++){
        v[j] = *reinterpret_cast<const float4*>(x + j*128 + lane*4);
        s += v[j].x + v[j].y + v[j].z + v[j].w;
    }
    #pragma unroll
    for (int o = 16; o; o >>= 1) s += __shfl_xor_sync(0xffffffffu, s, o);
    float mu = s / N;
    float var = 0.f;
    for (int j = 0; j < nch; j++){
        float dx = v[j].x-mu, dy = v[j].y-mu, dz = v[j].z-mu, dw = v[j].w-mu;
        var += dx*dx + dy*dy + dz*dz + dw*dw;
    }
    #pragma unroll
    for (int o = 16; o; o >>= 1) var += __shfl_xor_sync(0xffffffffu, var, o);
    float rstd = rsqrtf(var / N + eps);

    for (int j = 0; j < nch; j++){
        int c = j*128 + lane*4;
        float4 gg = *reinterpret_cast<const float4*>(g  + c);
        float4 bb = *reinterpret_cast<const float4*>(bt + c);
        float y0 = (v[j].x - mu) * rstd * gg.x + bb.x;
        float y1 = (v[j].y - mu) * rstd * gg.y + bb.y;
        float y2 = (v[j].z - mu) * rstd * gg.z + bb.z;
        float y3 = (v[j].w - mu) * rstd * gg.w + bb.w;
        if (out)
            *reinterpret_cast<float4*>(out + (size_t)row * N + c) =
                make_float4(y0, y1, y2, y3);
        if (outh){
            uint2 u;
            u.x = pack2(y0, y1);
            u.y = pack2(y2, y3);
            *reinterpret_cast<uint2*>(outh + (size_t)row * N + c) = u;
        }
    }
}

// ---------------- launch --------------------------------------------------------
extern "C" void kernel_launch(void* const* d_in, const int* in_sizes, int n_in,
                              void* d_out, int out_size)
{
    (void)in_sizes; (void)n_in; (void)out_size;
    const float* x    = (const float*)d_in[0];
    const float* mask = (const float*)d_in[1];
    const float* wq   = (const float*)d_in[2];
    const float* bq   = (const float*)d_in[3];
    const float* wk   = (const float*)d_in[4];
    const float* bk   = (const float*)d_in[5];
    const float* wv   = (const float*)d_in[6];
    const float* bv   = (const float*)d_in[7];
    const float* wo   = (const float*)d_in[8];
    const float* bo   = (const float*)d_in[9];
    const float* w1   = (const float*)d_in[10];
    const float* b1   = (const float*)d_in[11];
    const float* lnffg= (const float*)d_in[12];
    const float* lnffb= (const float*)d_in[13];
    const float* w2   = (const float*)d_in[14];
    const float* b2   = (const float*)d_in[15];
    const float* ln1g = (const float*)d_in[16];
    const float* ln1b = (const float*)d_in[17];
    const float* ln2g = (const float*)d_in[18];
    const float* ln2b = (const float*)d_in[19];
    float* out = (float*)d_out;

    float  *X1, *Hb, *negm, *bqkv;
    __half *xh, *QKVh, *ctxh, *x1h, *hh;
    __half *wqkvT, *woT, *w1T, *w2T;
    cudaGetSymbolAddress((void**)&X1,    g_X1);
    cudaGetSymbolAddress((void**)&Hb,    g_H);
    cudaGetSymbolAddress((void**)&negm,  g_negm);
    cudaGetSymbolAddress((void**)&bqkv,  g_bqkv);
    cudaGetSymbolAddress((void**)&xh,    g_xh);
    cudaGetSymbolAddress((void**)&QKVh,  g_QKVh);
    cudaGetSymbolAddress((void**)&ctxh,  g_ctxh);
    cudaGetSymbolAddress((void**)&x1h,   g_x1h);
    cudaGetSymbolAddress((void**)&hh,    g_hh);
    cudaGetSymbolAddress((void**)&wqkvT, g_wqkvT);
    cudaGetSymbolAddress((void**)&woT,   g_woT);
    cudaGetSymbolAddress((void**)&w1T,   g_w1T);
    cudaGetSymbolAddress((void**)&w2T,   g_w2T);

    cudaFuncSetAttribute(attn_h, cudaFuncAttributeMaxDynamicSharedMemorySize,
                         ATTN_SMEM_BYTES);
    cudaFuncSetAttribute(gemm_h<false,true>,  cudaFuncAttributeMaxDynamicSharedMemorySize, GEMM_SMEM_BYTES);
    cudaFuncSetAttribute(gemm_h<false,false>, cudaFuncAttributeMaxDynamicSharedMemorySize, GEMM_SMEM_BYTES);
    cudaFuncSetAttribute(gemm_h<true,false>,  cudaFuncAttributeMaxDynamicSharedMemorySize, GEMM_SMEM_BYTES);

    const dim3 blk(256);
    const dim3 gQKV(NQKV/64, MTOK/128);
    const dim3 gP(Dv/64,    MTOK/128);
    const dim3 gF(DFFv/64,  MTOK/128);

    // prep
    cvt_kernel<<<(MTOK*Dv/4 + 255)/256, blk>>>(x, xh, MTOK*Dv/4);
    prep_kernel<<<(NQKV + Bv*Sv + 255)/256, blk>>>(bq, bk, bv, mask, bqkv, negm);
    transp_all<<<768, dim3(32,8)>>>(wq, wk, wv, wo, w1, w2,
                                    wqkvT, woT, w1T, w2T);
    // fused QKV projection (half out, row stride 768)
    gemm_h<false,true><<<gQKV, blk, GEMM_SMEM_BYTES>>>(xh, wqkvT, bqkv, nullptr,
                                                       nullptr, QKVh, MTOK, NQKV, Dv);
    // attention
    attn_h<<<dim3(Sv/QROWS, Bv*Hv), blk, ATTN_SMEM_BYTES>>>(QKVh, negm, ctxh);
    // out-proj + residual, LN1
    gemm_h<false,false><<<gP, blk, GEMM_SMEM_BYTES>>>(ctxh, woT, bo, x, X1, nullptr,
                                                      MTOK, Dv, Dv);
    ln_kernel<<<MTOK/8, blk>>>(X1, X1, x1h, ln1g, ln1b, Dv, 1e-3f);
    // FFN1 + relu, LN_ff
    gemm_h<true,false><<<gF, blk, GEMM_SMEM_BYTES>>>(x1h, w1T, b1, nullptr, Hb, nullptr,
                                                     MTOK, DFFv, Dv);
    ln_kernel<<<MTOK/8, blk>>>(Hb, nullptr, hh, lnffg, lnffb, DFFv, 1e-6f);
    // FFN2 + residual, LN2
    gemm_h<false,false><<<gP, blk, GEMM_SMEM_BYTES>>>(hh, w2T, b2, X1, out, nullptr,
                                                      MTOK, Dv, DFFv);
    ln_kernel<<<MTOK/8, blk>>>(out, out, nullptr, ln2g, ln2b, Dv, 1e-3f);
}